// round 1
// baseline (speedup 1.0000x reference)
#include <cuda_runtime.h>
#include <cstdint>

#define NN 50000
#define NE 800000
#define IND 64
#define HD 128
#define OD 64
#define BN_EPS 1e-5f

// ---- scratch (no allocs allowed; __device__ globals) ----
__device__ __align__(256) float g_deg[NN];
__device__ __align__(256) float g_deginv[NN];
__device__ __align__(256) float g_agg1[NN * IND];
__device__ __align__(256) float g_hpre[NN * HD];
__device__ __align__(256) float g_agg2[NN * HD];
__device__ __align__(256) float g_bnsum[HD];
__device__ __align__(256) float g_bnsq[HD];
__device__ __align__(256) float g_scale[HD];
__device__ __align__(256) float g_shift[HD];

__device__ __forceinline__ void red_add_v4(float* addr, float4 v) {
    asm volatile("red.global.add.v4.f32 [%0], {%1,%2,%3,%4};"
                 :: "l"(addr), "f"(v.x), "f"(v.y), "f"(v.z), "f"(v.w)
                 : "memory");
}

// ---- zero scratch ----
__global__ void k_zero() {
    int i = blockIdx.x * blockDim.x + threadIdx.x;
    int stride = gridDim.x * blockDim.x;
    float4 z = make_float4(0.f, 0.f, 0.f, 0.f);
    for (int k = i; k < NN / 4; k += stride) ((float4*)g_deg)[k] = z;
    for (int k = i; k < NN * IND / 4; k += stride) ((float4*)g_agg1)[k] = z;
    for (int k = i; k < NN * HD / 4; k += stride) ((float4*)g_agg2)[k] = z;
    if (i < HD) { g_bnsum[i] = 0.f; g_bnsq[i] = 0.f; }
}

// ---- degree count ----
__global__ void k_deg(const int* __restrict__ dst) {
    int e = blockIdx.x * blockDim.x + threadIdx.x;
    if (e >= NE) return;
    atomicAdd(&g_deg[dst[e]], 1.0f);
}

__global__ void k_deginv() {
    int n = blockIdx.x * blockDim.x + threadIdx.x;
    if (n >= NN) return;
    float d = g_deg[n];
    g_deginv[n] = (d > 0.f) ? (1.0f / d) : 0.0f;
}

// ---- scatter layer 1: agg1[dst] += x[src]   (16 threads/edge, float4 each) ----
__global__ void k_scatter1(const float* __restrict__ x,
                           const int* __restrict__ src,
                           const int* __restrict__ dst) {
    int t = blockIdx.x * blockDim.x + threadIdx.x;
    int e = t >> 4;
    int c = t & 15;          // float4 chunk within 64-dim row
    if (e >= NE) return;
    int s = src[e];
    int d = dst[e];
    float4 v = ((const float4*)x)[s * (IND / 4) + c];
    red_add_v4(&g_agg1[d * IND + c * 4], v);
}

// ---- layer-1 dense: h_pre = (agg1*deginv)@W1l + b1 + x@W1r ; BN partial sums ----
#define NT1 32
__global__ void k_lin1(const float* __restrict__ x,
                       const float* __restrict__ W1l,
                       const float* __restrict__ b1,
                       const float* __restrict__ W1r) {
    __shared__ float sx[NT1][IND];
    __shared__ float sa[NT1][IND];
    const int n0 = blockIdx.x * NT1;
    const int tid = threadIdx.x;   // 128 threads

    // cooperative load of node tile (float4)
    for (int idx = tid; idx < NT1 * (IND / 4); idx += blockDim.x) {
        int r = idx / (IND / 4), c = idx % (IND / 4);
        int node = n0 + r;
        float4 vx = make_float4(0.f, 0.f, 0.f, 0.f);
        float4 va = vx;
        if (node < NN) {
            vx = ((const float4*)x)[node * (IND / 4) + c];
            float di = g_deginv[node];
            float4 t = ((const float4*)g_agg1)[node * (IND / 4) + c];
            va = make_float4(t.x * di, t.y * di, t.z * di, t.w * di);
        }
        ((float4*)&sx[r][0])[c] = vx;
        ((float4*)&sa[r][0])[c] = va;
    }
    __syncthreads();

    const int j = tid;  // output feature 0..127
    float acc[NT1];
    const float bj = b1[j];
#pragma unroll
    for (int n = 0; n < NT1; n++) acc[n] = bj;

    for (int k = 0; k < IND; k++) {
        float wl = W1l[k * HD + j];
        float wr = W1r[k * HD + j];
#pragma unroll
        for (int n = 0; n < NT1; n++)
            acc[n] += sa[n][k] * wl + sx[n][k] * wr;
    }

    float s = 0.f, sq = 0.f;
    int nmax = min(NT1, NN - n0);
    for (int n = 0; n < nmax; n++) {
        g_hpre[(n0 + n) * HD + j] = acc[n];
        s += acc[n];
        sq += acc[n] * acc[n];
    }
    atomicAdd(&g_bnsum[j], s);
    atomicAdd(&g_bnsq[j], sq);
}

// ---- BN finalize: scale/shift per feature ----
__global__ void k_bnfin(const float* __restrict__ gamma,
                        const float* __restrict__ beta) {
    int j = threadIdx.x;
    if (j >= HD) return;
    float mu = g_bnsum[j] * (1.0f / NN);
    float var = g_bnsq[j] * (1.0f / NN) - mu * mu;
    float sc = gamma[j] * rsqrtf(var + BN_EPS);
    g_scale[j] = sc;
    g_shift[j] = beta[j] - mu * sc;
}

// ---- scatter layer 2: agg2[dst] += relu(bn(h_pre[src]))  (32 threads/edge) ----
__global__ void k_scatter2(const int* __restrict__ src,
                           const int* __restrict__ dst) {
    int t = blockIdx.x * blockDim.x + threadIdx.x;
    int e = t >> 5;
    int c = t & 31;          // float4 chunk within 128-dim row
    if (e >= NE) return;
    int s = src[e];
    int d = dst[e];
    float4 h  = ((const float4*)g_hpre)[s * (HD / 4) + c];
    float4 sc = ((const float4*)g_scale)[c];
    float4 sh = ((const float4*)g_shift)[c];
    float4 v;
    v.x = fmaxf(fmaf(h.x, sc.x, sh.x), 0.f);
    v.y = fmaxf(fmaf(h.y, sc.y, sh.y), 0.f);
    v.z = fmaxf(fmaf(h.z, sc.z, sh.z), 0.f);
    v.w = fmaxf(fmaf(h.w, sc.w, sh.w), 0.f);
    red_add_v4(&g_agg2[d * HD + c * 4], v);
}

// ---- layer-2 dense: out = (agg2*deginv)@W2l + b2 + relu(bn(h_pre))@W2r ----
#define NT2 32
__global__ void k_lin2(const float* __restrict__ W2l,
                       const float* __restrict__ b2,
                       const float* __restrict__ W2r,
                       float* __restrict__ out) {
    __shared__ float sh_[NT2][HD];
    __shared__ float sa[NT2][HD];
    const int n0 = blockIdx.x * NT2;
    const int tid = threadIdx.x;   // 64 threads

    for (int idx = tid; idx < NT2 * (HD / 4); idx += blockDim.x) {
        int r = idx / (HD / 4), c = idx % (HD / 4);
        int node = n0 + r;
        float4 vh = make_float4(0.f, 0.f, 0.f, 0.f);
        float4 va = vh;
        if (node < NN) {
            float4 h  = ((const float4*)g_hpre)[node * (HD / 4) + c];
            float4 sc = ((const float4*)g_scale)[c];
            float4 sf = ((const float4*)g_shift)[c];
            vh.x = fmaxf(fmaf(h.x, sc.x, sf.x), 0.f);
            vh.y = fmaxf(fmaf(h.y, sc.y, sf.y), 0.f);
            vh.z = fmaxf(fmaf(h.z, sc.z, sf.z), 0.f);
            vh.w = fmaxf(fmaf(h.w, sc.w, sf.w), 0.f);
            float di = g_deginv[node];
            float4 t = ((const float4*)g_agg2)[node * (HD / 4) + c];
            va = make_float4(t.x * di, t.y * di, t.z * di, t.w * di);
        }
        ((float4*)&sh_[r][0])[c] = vh;
        ((float4*)&sa[r][0])[c] = va;
    }
    __syncthreads();

    const int j = tid;  // output feature 0..63
    float acc[NT2];
    const float bj = b2[j];
#pragma unroll
    for (int n = 0; n < NT2; n++) acc[n] = bj;

    for (int k = 0; k < HD; k++) {
        float wl = W2l[k * OD + j];
        float wr = W2r[k * OD + j];
#pragma unroll
        for (int n = 0; n < NT2; n++)
            acc[n] += sa[n][k] * wl + sh_[n][k] * wr;
    }

    int nmax = min(NT2, NN - n0);
    for (int n = 0; n < nmax; n++)
        out[(n0 + n) * OD + j] = acc[n];
}

extern "C" void kernel_launch(void* const* d_in, const int* in_sizes, int n_in,
                              void* d_out, int out_size) {
    const float* x     = (const float*)d_in[0];
    const int*   ei    = (const int*)d_in[1];
    const float* W1l   = (const float*)d_in[2];
    const float* b1    = (const float*)d_in[3];
    const float* W1r   = (const float*)d_in[4];
    const float* gamma = (const float*)d_in[5];
    const float* beta  = (const float*)d_in[6];
    const float* W2l   = (const float*)d_in[7];
    const float* b2    = (const float*)d_in[8];
    const float* W2r   = (const float*)d_in[9];
    float* out = (float*)d_out;

    const int* src = ei;
    const int* dst = ei + NE;

    k_zero<<<1024, 256>>>();
    k_deg<<<(NE + 511) / 512, 512>>>(dst);
    k_deginv<<<(NN + 255) / 256, 256>>>();
    k_scatter1<<<(NE * 16 + 255) / 256, 256>>>(x, src, dst);
    k_lin1<<<(NN + NT1 - 1) / NT1, 128>>>(x, W1l, b1, W1r);
    k_bnfin<<<1, 128>>>(gamma, beta);
    k_scatter2<<<(NE * 32 + 255) / 256, 256>>>(src, dst);
    k_lin2<<<(NN + NT2 - 1) / NT2, 64>>>(W2l, b2, W2r, out);
}

// round 2
// speedup vs baseline: 1.7308x; 1.7308x over previous
#include <cuda_runtime.h>

#define NN 50000
#define NE 800000
#define IND 64
#define HD 128
#define OD 64
#define BN_EPS 1e-5f

// ---- scratch (__device__ globals; no allocs) ----
__device__ __align__(256) int   g_degi[NN];
__device__ __align__(256) int   g_off[NN + 1];
__device__ __align__(256) int   g_cur[NN];
__device__ __align__(256) int   g_esrc[NE];
__device__ __align__(256) float g_deginv[NN];
__device__ __align__(256) float g_agg1[NN * IND];   // mean-aggregated, deginv applied
__device__ __align__(256) float g_hpre[NN * HD];    // pre-BN layer-1 output
__device__ __align__(256) float g_agg2[NN * HD];    // mean-aggregated relu(bn(h))
__device__ __align__(256) float g_bnsum[HD];
__device__ __align__(256) float g_bnsq[HD];
__device__ __align__(256) float g_scale[HD];
__device__ __align__(256) float g_shift[HD];

// ---- zero the small stuff ----
__global__ void k_zero() {
    int i = blockIdx.x * blockDim.x + threadIdx.x;
    int stride = gridDim.x * blockDim.x;
    for (int k = i; k < NN; k += stride) g_degi[k] = 0;
    if (i < HD) { g_bnsum[i] = 0.f; g_bnsq[i] = 0.f; }
}

// ---- degree histogram ----
__global__ void k_deg(const int* __restrict__ dst) {
    int e = blockIdx.x * blockDim.x + threadIdx.x;
    if (e < NE) atomicAdd(&g_degi[dst[e]], 1);
}

// ---- single-block exclusive scan over degrees -> CSR offsets + cursors + deginv ----
__global__ void k_scan() {
    __shared__ int wsum[32];
    const int tid = threadIdx.x, lane = tid & 31, w = tid >> 5;
    int carry = 0;
    for (int base = 0; base < NN; base += 1024) {
        int i = base + tid;
        int v = (i < NN) ? g_degi[i] : 0;
        int s = v;
#pragma unroll
        for (int o = 1; o < 32; o <<= 1) {
            int t = __shfl_up_sync(0xffffffffu, s, o);
            if (lane >= o) s += t;
        }
        if (lane == 31) wsum[w] = s;
        __syncthreads();
        if (w == 0) {
            int ws = wsum[lane];
#pragma unroll
            for (int o = 1; o < 32; o <<= 1) {
                int t = __shfl_up_sync(0xffffffffu, ws, o);
                if (lane >= o) ws += t;
            }
            wsum[lane] = ws;
        }
        __syncthreads();
        int wpre = (w == 0) ? 0 : wsum[w - 1];
        int total = wsum[31];
        int excl = carry + wpre + s - v;
        if (i < NN) {
            g_off[i] = excl;
            g_cur[i] = excl;
            g_deginv[i] = (v > 0) ? (1.0f / (float)v) : 0.0f;
        }
        carry += total;
        __syncthreads();
    }
    if (tid == 0) g_off[NN] = carry;
}

// ---- CSR fill: bucket src ids by dst ----
__global__ void k_fill(const int* __restrict__ src, const int* __restrict__ dst) {
    int e = blockIdx.x * blockDim.x + threadIdx.x;
    if (e >= NE) return;
    int p = atomicAdd(&g_cur[dst[e]], 1);
    g_esrc[p] = src[e];
}

// ---- layer-1 mean aggregation: 16 threads per node, gather + reg accumulate ----
__global__ void k_agg1(const float* __restrict__ x) {
    int t = blockIdx.x * blockDim.x + threadIdx.x;
    int node = t >> 4, c = t & 15;
    if (node >= NN) return;
    int beg = g_off[node], end = g_off[node + 1];
    float4 acc = make_float4(0.f, 0.f, 0.f, 0.f);
    for (int j = beg; j < end; j++) {
        int s = g_esrc[j];
        float4 v = ((const float4*)x)[s * (IND / 4) + c];
        acc.x += v.x; acc.y += v.y; acc.z += v.z; acc.w += v.w;
    }
    float di = g_deginv[node];
    acc.x *= di; acc.y *= di; acc.z *= di; acc.w *= di;
    ((float4*)g_agg1)[node * (IND / 4) + c] = acc;
}

// ---- layer-1 dense: h_pre = agg1@W1l + b1 + x@W1r ; BN partials ----
#define NT1 32
__global__ void k_lin1(const float* __restrict__ x,
                       const float* __restrict__ W1l,
                       const float* __restrict__ b1,
                       const float* __restrict__ W1r) {
    __shared__ float sa[NT1][IND];
    __shared__ float sx[NT1][IND];
    const int n0 = blockIdx.x * NT1;
    const int tid = threadIdx.x;   // 256 threads

    for (int idx = tid; idx < NT1 * (IND / 4); idx += 256) {
        int r = idx >> 4, c = idx & 15;
        int node = n0 + r;
        float4 vx = make_float4(0.f, 0.f, 0.f, 0.f);
        float4 va = vx;
        if (node < NN) {
            vx = ((const float4*)x)[node * (IND / 4) + c];
            va = ((const float4*)g_agg1)[node * (IND / 4) + c];
        }
        ((float4*)&sx[r][0])[c] = vx;
        ((float4*)&sa[r][0])[c] = va;
    }
    __syncthreads();

    const int j = tid & 127;        // output feature
    const int bn = (tid >> 7) * 16; // node half
    float acc[16];
    const float bj = b1[j];
#pragma unroll
    for (int n = 0; n < 16; n++) acc[n] = bj;

    for (int k = 0; k < IND; k += 4) {
        float wl0 = W1l[(k + 0) * HD + j];
        float wl1 = W1l[(k + 1) * HD + j];
        float wl2 = W1l[(k + 2) * HD + j];
        float wl3 = W1l[(k + 3) * HD + j];
        float wr0 = W1r[(k + 0) * HD + j];
        float wr1 = W1r[(k + 1) * HD + j];
        float wr2 = W1r[(k + 2) * HD + j];
        float wr3 = W1r[(k + 3) * HD + j];
#pragma unroll
        for (int n = 0; n < 16; n++) {
            float4 a  = *(const float4*)&sa[bn + n][k];
            float4 xx = *(const float4*)&sx[bn + n][k];
            acc[n] += a.x * wl0 + a.y * wl1 + a.z * wl2 + a.w * wl3
                    + xx.x * wr0 + xx.y * wr1 + xx.z * wr2 + xx.w * wr3;
        }
    }

    float s = 0.f, sq = 0.f;
#pragma unroll
    for (int n = 0; n < 16; n++) {
        int node = n0 + bn + n;
        if (node < NN) {
            float v = acc[n];
            g_hpre[node * HD + j] = v;
            s += v;
            sq += v * v;
        }
    }
    atomicAdd(&g_bnsum[j], s);
    atomicAdd(&g_bnsq[j], sq);
}

// ---- BN finalize ----
__global__ void k_bnfin(const float* __restrict__ gamma,
                        const float* __restrict__ beta) {
    int j = threadIdx.x;
    if (j >= HD) return;
    float mu = g_bnsum[j] * (1.0f / NN);
    float var = g_bnsq[j] * (1.0f / NN) - mu * mu;
    float sc = gamma[j] * rsqrtf(var + BN_EPS);
    g_scale[j] = sc;
    g_shift[j] = beta[j] - mu * sc;
}

// ---- layer-2 mean aggregation: 32 threads per node, BN+ReLU fused in gather ----
__global__ void k_agg2() {
    int t = blockIdx.x * blockDim.x + threadIdx.x;
    int node = t >> 5, c = t & 31;
    if (node >= NN) return;
    float4 sc = ((const float4*)g_scale)[c];
    float4 sh = ((const float4*)g_shift)[c];
    int beg = g_off[node], end = g_off[node + 1];
    float4 acc = make_float4(0.f, 0.f, 0.f, 0.f);
    for (int j = beg; j < end; j++) {
        int s = g_esrc[j];
        float4 h = ((const float4*)g_hpre)[s * (HD / 4) + c];
        acc.x += fmaxf(fmaf(h.x, sc.x, sh.x), 0.f);
        acc.y += fmaxf(fmaf(h.y, sc.y, sh.y), 0.f);
        acc.z += fmaxf(fmaf(h.z, sc.z, sh.z), 0.f);
        acc.w += fmaxf(fmaf(h.w, sc.w, sh.w), 0.f);
    }
    float di = g_deginv[node];
    acc.x *= di; acc.y *= di; acc.z *= di; acc.w *= di;
    ((float4*)g_agg2)[node * (HD / 4) + c] = acc;
}

// ---- layer-2 dense: out = agg2@W2l + b2 + relu(bn(h_pre))@W2r ----
#define NT2 32
__global__ void k_lin2(const float* __restrict__ W2l,
                       const float* __restrict__ b2,
                       const float* __restrict__ W2r,
                       float* __restrict__ out) {
    __shared__ float sh_[NT2][HD];
    __shared__ float sg[NT2][HD];
    const int n0 = blockIdx.x * NT2;
    const int tid = threadIdx.x;   // 256 threads

    for (int idx = tid; idx < NT2 * (HD / 4); idx += 256) {
        int r = idx >> 5, c = idx & 31;
        int node = n0 + r;
        float4 vh = make_float4(0.f, 0.f, 0.f, 0.f);
        float4 va = vh;
        if (node < NN) {
            float4 h  = ((const float4*)g_hpre)[node * (HD / 4) + c];
            float4 sc = ((const float4*)g_scale)[c];
            float4 sf = ((const float4*)g_shift)[c];
            vh.x = fmaxf(fmaf(h.x, sc.x, sf.x), 0.f);
            vh.y = fmaxf(fmaf(h.y, sc.y, sf.y), 0.f);
            vh.z = fmaxf(fmaf(h.z, sc.z, sf.z), 0.f);
            vh.w = fmaxf(fmaf(h.w, sc.w, sf.w), 0.f);
            va = ((const float4*)g_agg2)[node * (HD / 4) + c];
        }
        ((float4*)&sh_[r][0])[c] = vh;
        ((float4*)&sg[r][0])[c] = va;
    }
    __syncthreads();

    const int j = tid & 63;        // output feature
    const int bn = (tid >> 6) * 8; // node quarter
    float acc[8];
    const float bj = b2[j];
#pragma unroll
    for (int n = 0; n < 8; n++) acc[n] = bj;

    for (int k = 0; k < HD; k += 4) {
        float wl0 = W2l[(k + 0) * OD + j];
        float wl1 = W2l[(k + 1) * OD + j];
        float wl2 = W2l[(k + 2) * OD + j];
        float wl3 = W2l[(k + 3) * OD + j];
        float wr0 = W2r[(k + 0) * OD + j];
        float wr1 = W2r[(k + 1) * OD + j];
        float wr2 = W2r[(k + 2) * OD + j];
        float wr3 = W2r[(k + 3) * OD + j];
#pragma unroll
        for (int n = 0; n < 8; n++) {
            float4 a = *(const float4*)&sg[bn + n][k];
            float4 h = *(const float4*)&sh_[bn + n][k];
            acc[n] += a.x * wl0 + a.y * wl1 + a.z * wl2 + a.w * wl3
                    + h.x * wr0 + h.y * wr1 + h.z * wr2 + h.w * wr3;
        }
    }

#pragma unroll
    for (int n = 0; n < 8; n++) {
        int node = n0 + bn + n;
        if (node < NN) out[node * OD + j] = acc[n];
    }
}

extern "C" void kernel_launch(void* const* d_in, const int* in_sizes, int n_in,
                              void* d_out, int out_size) {
    const float* x     = (const float*)d_in[0];
    const int*   ei    = (const int*)d_in[1];
    const float* W1l   = (const float*)d_in[2];
    const float* b1    = (const float*)d_in[3];
    const float* W1r   = (const float*)d_in[4];
    const float* gamma = (const float*)d_in[5];
    const float* beta  = (const float*)d_in[6];
    const float* W2l   = (const float*)d_in[7];
    const float* b2    = (const float*)d_in[8];
    const float* W2r   = (const float*)d_in[9];
    float* out = (float*)d_out;

    const int* src = ei;
    const int* dst = ei + NE;

    k_zero<<<(NN + 255) / 256, 256>>>();
    k_deg<<<(NE + 511) / 512, 512>>>(dst);
    k_scan<<<1, 1024>>>();
    k_fill<<<(NE + 255) / 256, 256>>>(src, dst);
    k_agg1<<<(NN * 16 + 255) / 256, 256>>>(x);
    k_lin1<<<(NN + NT1 - 1) / NT1, 256>>>(x, W1l, b1, W1r);
    k_bnfin<<<1, 128>>>(gamma, beta);
    k_agg2<<<(NN * 32 + 255) / 256, 256>>>();
    k_lin2<<<(NN + NT2 - 1) / NT2, 256>>>(W2l, b2, W2r, out);
}

// round 3
// speedup vs baseline: 2.2188x; 1.2819x over previous
#include <cuda_runtime.h>
#include <cuda_fp16.h>

#define NN 50000
#define NE 800000
#define IND 64
#define HD 128
#define OD 64
#define BN_EPS 1e-5f
#define NB 49   // scan blocks: ceil(NN/1024)

typedef unsigned long long ull;

// ---- scratch (__device__ globals; no allocs) ----
__device__ __align__(256) int    g_degi[NN];
__device__ __align__(256) int    g_off[NN + 1];
__device__ __align__(256) int    g_cur[NN];
__device__ __align__(256) int    g_esrc[NE];
__device__ __align__(256) int    g_bsums[NB];
__device__ __align__(256) float  g_deginv[NN];
__device__ __align__(256) __half g_xh[NN * IND];      // fp16 copy of x (gather side)
__device__ __align__(256) float  g_agg1[NN * IND];    // mean-agg of x (fp32)
__device__ __align__(256) float  g_hpre[NN * HD];     // pre-BN layer-1 out (fp32)
__device__ __align__(256) __half g_hrelu[NN * HD];    // relu(bn(hpre)) fp16 (gather side)
__device__ __align__(256) float  g_agg2[NN * HD];     // mean-agg of hrelu (fp32)
__device__ __align__(256) float  g_bnsum[HD];
__device__ __align__(256) float  g_bnsq[HD];
__device__ __align__(256) float  g_scale[HD];
__device__ __align__(256) float  g_shift[HD];
// packed weight pairs: (W[2k][j], W[2k+1][j]) as f32x2
__device__ __align__(256) ull    g_w1l[(IND / 2) * HD];
__device__ __align__(256) ull    g_w1r[(IND / 2) * HD];
__device__ __align__(256) ull    g_w2l[(HD / 2) * OD];
__device__ __align__(256) ull    g_w2r[(HD / 2) * OD];

__device__ __forceinline__ ull pack2(float x, float y) {
    ull r;
    asm("mov.b64 %0, {%1,%2};" : "=l"(r) : "f"(x), "f"(y));
    return r;
}
__device__ __forceinline__ float2 unpack2(ull v) {
    float2 r;
    asm("mov.b64 {%0,%1}, %2;" : "=f"(r.x), "=f"(r.y) : "l"(v));
    return r;
}
__device__ __forceinline__ void ffma2(ull& d, ull a, ull b) {
    asm("fma.rn.f32x2 %0, %1, %2, %0;" : "+l"(d) : "l"(a), "l"(b));
}

// ---- prep: zero counters, pack weights, convert x->fp16 ----
__global__ void k_prep(const float* __restrict__ x,
                       const float* __restrict__ W1l, const float* __restrict__ W1r,
                       const float* __restrict__ W2l, const float* __restrict__ W2r) {
    int t = blockIdx.x * blockDim.x + threadIdx.x;
    int stride = gridDim.x * blockDim.x;
    for (int i = t; i < NN; i += stride) g_degi[i] = 0;
    if (t < HD) { g_bnsum[t] = 0.f; g_bnsq[t] = 0.f; }
    for (int i = t; i < (IND / 2) * HD; i += stride) {
        int kp = i >> 7, j = i & 127;
        g_w1l[i] = pack2(W1l[(2 * kp) * HD + j], W1l[(2 * kp + 1) * HD + j]);
        g_w1r[i] = pack2(W1r[(2 * kp) * HD + j], W1r[(2 * kp + 1) * HD + j]);
    }
    for (int i = t; i < (HD / 2) * OD; i += stride) {
        int kp = i >> 6, j = i & 63;
        g_w2l[i] = pack2(W2l[(2 * kp) * OD + j], W2l[(2 * kp + 1) * OD + j]);
        g_w2r[i] = pack2(W2r[(2 * kp) * OD + j], W2r[(2 * kp + 1) * OD + j]);
    }
    for (int i = t; i < NN * IND / 4; i += stride) {
        float4 v = ((const float4*)x)[i];
        __half2 a = __floats2half2_rn(v.x, v.y);
        __half2 b = __floats2half2_rn(v.z, v.w);
        uint2 u;
        u.x = *reinterpret_cast<unsigned int*>(&a);
        u.y = *reinterpret_cast<unsigned int*>(&b);
        ((uint2*)g_xh)[i] = u;
    }
}

// ---- degree histogram, 4 edges/thread ----
__global__ void k_deg(const int* __restrict__ dst) {
    int t = blockIdx.x * blockDim.x + threadIdx.x;
    if (t * 4 >= NE) return;
    int4 d = ((const int4*)dst)[t];
    atomicAdd(&g_degi[d.x], 1);
    atomicAdd(&g_degi[d.y], 1);
    atomicAdd(&g_degi[d.z], 1);
    atomicAdd(&g_degi[d.w], 1);
}

// ---- scan stage 1: per-block exclusive scan ----
__global__ void k_scan1() {
    __shared__ int ws[32];
    int tid = threadIdx.x, lane = tid & 31, w = tid >> 5;
    int i = blockIdx.x * 1024 + tid;
    int v = (i < NN) ? g_degi[i] : 0;
    int s = v;
#pragma unroll
    for (int o = 1; o < 32; o <<= 1) {
        int tt = __shfl_up_sync(0xffffffffu, s, o);
        if (lane >= o) s += tt;
    }
    if (lane == 31) ws[w] = s;
    __syncthreads();
    if (w == 0) {
        int t2 = ws[lane];
#pragma unroll
        for (int o = 1; o < 32; o <<= 1) {
            int tt = __shfl_up_sync(0xffffffffu, t2, o);
            if (lane >= o) t2 += tt;
        }
        ws[lane] = t2;
    }
    __syncthreads();
    int excl = ((w > 0) ? ws[w - 1] : 0) + s - v;
    if (i < NN) g_off[i] = excl;
    if (tid == 1023) g_bsums[blockIdx.x] = ws[31];
}

// ---- scan stage 2: scan the 49 block sums ----
__global__ void k_scan2() {
    __shared__ int wtot;
    int tid = threadIdx.x, lane = tid & 31, w = tid >> 5;
    int v = (tid < NB) ? g_bsums[tid] : 0;
    int s = v;
#pragma unroll
    for (int o = 1; o < 32; o <<= 1) {
        int tt = __shfl_up_sync(0xffffffffu, s, o);
        if (lane >= o) s += tt;
    }
    if (w == 0 && lane == 31) wtot = s;
    __syncthreads();
    int incl = s + ((w == 1) ? wtot : 0);
    if (tid < NB) g_bsums[tid] = incl - v;
}

// ---- scan stage 3: combine, write offsets/cursors/deginv ----
__global__ void k_scan3() {
    int i = blockIdx.x * 1024 + threadIdx.x;
    if (i < NN) {
        int off = g_off[i] + g_bsums[blockIdx.x];
        g_off[i] = off;
        g_cur[i] = off;
        int d = g_degi[i];
        g_deginv[i] = (d > 0) ? (1.0f / (float)d) : 0.0f;
    }
    if (i == 0) g_off[NN] = NE;
}

// ---- CSR fill, 4 edges/thread ----
__global__ void k_fill(const int* __restrict__ src, const int* __restrict__ dst) {
    int t = blockIdx.x * blockDim.x + threadIdx.x;
    if (t * 4 >= NE) return;
    int4 s4 = ((const int4*)src)[t];
    int4 d4 = ((const int4*)dst)[t];
    int p0 = atomicAdd(&g_cur[d4.x], 1);
    int p1 = atomicAdd(&g_cur[d4.y], 1);
    int p2 = atomicAdd(&g_cur[d4.z], 1);
    int p3 = atomicAdd(&g_cur[d4.w], 1);
    g_esrc[p0] = s4.x;
    g_esrc[p1] = s4.y;
    g_esrc[p2] = s4.z;
    g_esrc[p3] = s4.w;
}

// ---- layer-1 mean aggregation: 8 threads/node, fp16 gather ----
__global__ void k_agg1() {
    int t = blockIdx.x * blockDim.x + threadIdx.x;
    int node = t >> 3, c = t & 7;
    if (node >= NN) return;
    int beg = g_off[node], end = g_off[node + 1];
    float2 a0 = {0.f, 0.f}, a1 = a0, a2 = a0, a3 = a0;
    for (int j = beg; j < end; j++) {
        int s = g_esrc[j];
        uint4 r = ((const uint4*)g_xh)[s * 8 + c];
        float2 f0 = __half22float2(*(__half2*)&r.x);
        float2 f1 = __half22float2(*(__half2*)&r.y);
        float2 f2 = __half22float2(*(__half2*)&r.z);
        float2 f3 = __half22float2(*(__half2*)&r.w);
        a0.x += f0.x; a0.y += f0.y; a1.x += f1.x; a1.y += f1.y;
        a2.x += f2.x; a2.y += f2.y; a3.x += f3.x; a3.y += f3.y;
    }
    float di = g_deginv[node];
    float4 o0 = make_float4(a0.x * di, a0.y * di, a1.x * di, a1.y * di);
    float4 o1 = make_float4(a2.x * di, a2.y * di, a3.x * di, a3.y * di);
    ((float4*)g_agg1)[node * (IND / 4) + c * 2 + 0] = o0;
    ((float4*)g_agg1)[node * (IND / 4) + c * 2 + 1] = o1;
}

// ---- layer-1 dense (FFMA2): h_pre = agg1@W1l + b1 + x@W1r ; BN partials ----
#define NT1 32
__global__ void __launch_bounds__(128) k_lin1(const float* __restrict__ x,
                                              const float* __restrict__ b1) {
    __shared__ float sa[NT1][IND];
    __shared__ float sx[NT1][IND];
    const int n0 = blockIdx.x * NT1;
    const int tid = threadIdx.x;   // 128

    for (int idx = tid; idx < NT1 * (IND / 4); idx += 128) {
        int r = idx >> 4, c = idx & 15;
        int node = n0 + r;
        float4 va = make_float4(0.f, 0.f, 0.f, 0.f), vx = va;
        if (node < NN) {
            va = ((const float4*)g_agg1)[node * 16 + c];
            vx = ((const float4*)x)[node * 16 + c];
        }
        *(float4*)&sa[r][4 * c] = va;
        *(float4*)&sx[r][4 * c] = vx;
    }
    __syncthreads();

    const int j = tid;   // 0..127
    ull acc[NT1];
#pragma unroll
    for (int n = 0; n < NT1; n++) acc[n] = 0ull;

    for (int kq = 0; kq < IND / 4; kq++) {
        ull wl01 = g_w1l[(2 * kq) * HD + j];
        ull wl23 = g_w1l[(2 * kq + 1) * HD + j];
        ull wr01 = g_w1r[(2 * kq) * HD + j];
        ull wr23 = g_w1r[(2 * kq + 1) * HD + j];
#pragma unroll
        for (int n = 0; n < NT1; n++) {
            ulonglong2 a = *(const ulonglong2*)&sa[n][4 * kq];
            ulonglong2 xx = *(const ulonglong2*)&sx[n][4 * kq];
            ffma2(acc[n], a.x, wl01);
            ffma2(acc[n], a.y, wl23);
            ffma2(acc[n], xx.x, wr01);
            ffma2(acc[n], xx.y, wr23);
        }
    }

    const float bj = b1[j];
    float s = 0.f, sq = 0.f;
#pragma unroll
    for (int n = 0; n < NT1; n++) {
        int node = n0 + n;
        if (node < NN) {
            float2 p = unpack2(acc[n]);
            float v = p.x + p.y + bj;
            g_hpre[node * HD + j] = v;
            s += v;
            sq += v * v;
        }
    }
    atomicAdd(&g_bnsum[j], s);
    atomicAdd(&g_bnsq[j], sq);
}

// ---- BN finalize ----
__global__ void k_bnfin(const float* __restrict__ gamma,
                        const float* __restrict__ beta) {
    int j = threadIdx.x;
    if (j >= HD) return;
    float mu = g_bnsum[j] * (1.0f / NN);
    float var = g_bnsq[j] * (1.0f / NN) - mu * mu;
    float sc = gamma[j] * rsqrtf(var + BN_EPS);
    g_scale[j] = sc;
    g_shift[j] = beta[j] - mu * sc;
}

// ---- hrelu: g_hrelu = fp16(relu(bn(hpre))) ----
__global__ void k_hrelu() {
    int i = blockIdx.x * blockDim.x + threadIdx.x;
    if (i >= NN * HD / 4) return;
    int c = i & 31;
    float4 h = ((const float4*)g_hpre)[i];
    float4 sc = ((const float4*)g_scale)[c];
    float4 sh = ((const float4*)g_shift)[c];
    float4 v;
    v.x = fmaxf(fmaf(h.x, sc.x, sh.x), 0.f);
    v.y = fmaxf(fmaf(h.y, sc.y, sh.y), 0.f);
    v.z = fmaxf(fmaf(h.z, sc.z, sh.z), 0.f);
    v.w = fmaxf(fmaf(h.w, sc.w, sh.w), 0.f);
    __half2 a = __floats2half2_rn(v.x, v.y);
    __half2 b = __floats2half2_rn(v.z, v.w);
    uint2 u;
    u.x = *reinterpret_cast<unsigned int*>(&a);
    u.y = *reinterpret_cast<unsigned int*>(&b);
    ((uint2*)g_hrelu)[i] = u;
}

// ---- layer-2 mean aggregation: 16 threads/node, fp16 gather ----
__global__ void k_agg2() {
    int t = blockIdx.x * blockDim.x + threadIdx.x;
    int node = t >> 4, c = t & 15;
    if (node >= NN) return;
    int beg = g_off[node], end = g_off[node + 1];
    float2 a0 = {0.f, 0.f}, a1 = a0, a2 = a0, a3 = a0;
    for (int j = beg; j < end; j++) {
        int s = g_esrc[j];
        uint4 r = ((const uint4*)g_hrelu)[s * 16 + c];
        float2 f0 = __half22float2(*(__half2*)&r.x);
        float2 f1 = __half22float2(*(__half2*)&r.y);
        float2 f2 = __half22float2(*(__half2*)&r.z);
        float2 f3 = __half22float2(*(__half2*)&r.w);
        a0.x += f0.x; a0.y += f0.y; a1.x += f1.x; a1.y += f1.y;
        a2.x += f2.x; a2.y += f2.y; a3.x += f3.x; a3.y += f3.y;
    }
    float di = g_deginv[node];
    float4 o0 = make_float4(a0.x * di, a0.y * di, a1.x * di, a1.y * di);
    float4 o1 = make_float4(a2.x * di, a2.y * di, a3.x * di, a3.y * di);
    ((float4*)g_agg2)[node * (HD / 4) + c * 2 + 0] = o0;
    ((float4*)g_agg2)[node * (HD / 4) + c * 2 + 1] = o1;
}

// ---- layer-2 dense (FFMA2): out = agg2@W2l + b2 + relu(bn(hpre))@W2r ----
#define NT2 32
__global__ void __launch_bounds__(64) k_lin2(const float* __restrict__ b2,
                                             float* __restrict__ out) {
    __shared__ float sg[NT2][HD];
    __shared__ float sh_[NT2][HD];
    const int n0 = blockIdx.x * NT2;
    const int tid = threadIdx.x;   // 64

    for (int idx = tid; idx < NT2 * (HD / 4); idx += 64) {
        int r = idx >> 5, c = idx & 31;
        int node = n0 + r;
        float4 vg = make_float4(0.f, 0.f, 0.f, 0.f), vh = vg;
        if (node < NN) {
            vg = ((const float4*)g_agg2)[node * 32 + c];
            float4 h  = ((const float4*)g_hpre)[node * 32 + c];
            float4 sc = ((const float4*)g_scale)[c];
            float4 sf = ((const float4*)g_shift)[c];
            vh.x = fmaxf(fmaf(h.x, sc.x, sf.x), 0.f);
            vh.y = fmaxf(fmaf(h.y, sc.y, sf.y), 0.f);
            vh.z = fmaxf(fmaf(h.z, sc.z, sf.z), 0.f);
            vh.w = fmaxf(fmaf(h.w, sc.w, sf.w), 0.f);
        }
        *(float4*)&sg[r][4 * c] = vg;
        *(float4*)&sh_[r][4 * c] = vh;
    }
    __syncthreads();

    const int j = tid;   // 0..63
    ull acc[NT2];
#pragma unroll
    for (int n = 0; n < NT2; n++) acc[n] = 0ull;

    for (int kq = 0; kq < HD / 4; kq++) {
        ull wl01 = g_w2l[(2 * kq) * OD + j];
        ull wl23 = g_w2l[(2 * kq + 1) * OD + j];
        ull wr01 = g_w2r[(2 * kq) * OD + j];
        ull wr23 = g_w2r[(2 * kq + 1) * OD + j];
#pragma unroll
        for (int n = 0; n < NT2; n++) {
            ulonglong2 a = *(const ulonglong2*)&sg[n][4 * kq];
            ulonglong2 h = *(const ulonglong2*)&sh_[n][4 * kq];
            ffma2(acc[n], a.x, wl01);
            ffma2(acc[n], a.y, wl23);
            ffma2(acc[n], h.x, wr01);
            ffma2(acc[n], h.y, wr23);
        }
    }

    const float bj = b2[j];
#pragma unroll
    for (int n = 0; n < NT2; n++) {
        int node = n0 + n;
        if (node < NN) {
            float2 p = unpack2(acc[n]);
            out[node * OD + j] = p.x + p.y + bj;
        }
    }
}

extern "C" void kernel_launch(void* const* d_in, const int* in_sizes, int n_in,
                              void* d_out, int out_size) {
    const float* x     = (const float*)d_in[0];
    const int*   ei    = (const int*)d_in[1];
    const float* W1l   = (const float*)d_in[2];
    const float* b1    = (const float*)d_in[3];
    const float* W1r   = (const float*)d_in[4];
    const float* gamma = (const float*)d_in[5];
    const float* beta  = (const float*)d_in[6];
    const float* W2l   = (const float*)d_in[7];
    const float* b2    = (const float*)d_in[8];
    const float* W2r   = (const float*)d_in[9];
    float* out = (float*)d_out;

    const int* src = ei;
    const int* dst = ei + NE;

    k_prep<<<3125, 256>>>(x, W1l, W1r, W2l, W2r);
    k_deg<<<(NE / 4 + 255) / 256, 256>>>(dst);
    k_scan1<<<NB, 1024>>>();
    k_scan2<<<1, 64>>>();
    k_scan3<<<NB, 1024>>>();
    k_fill<<<(NE / 4 + 255) / 256, 256>>>(src, dst);
    k_agg1<<<(NN * 8 + 255) / 256, 256>>>();
    k_lin1<<<(NN + NT1 - 1) / NT1, 128>>>(x, b1);
    k_bnfin<<<1, 128>>>(gamma, beta);
    k_hrelu<<<(NN * HD / 4 + 255) / 256, 256>>>();
    k_agg2<<<(NN * 16 + 255) / 256, 256>>>();
    k_lin2<<<(NN + NT2 - 1) / NT2, 64>>>(b2, out);
}